// round 4
// baseline (speedup 1.0000x reference)
#include <cuda_runtime.h>

#define GSZ   52
#define NANCH 3
#define NCELL (GSZ * GSZ * NANCH)   // 8112
#define REC   85
#define MAXB  64
#define MAXGT 64
#define IMGSZ 416.0f
#define RATIO 8.0f
#define KAB   4                     // kA blocks per batch (4*256*8 = 8192 >= 8112)
#define KAT   256
#define KAI   8
#define TX    8
#define TY    8
#define TILES 7
#define NTILE (TILES * TILES)       // 49
#define KBT   192

// ---- scratch (device globals; zero-init at load) ----
__device__ float4   g_gt[MAXB][MAXGT];
__device__ int      g_cnt[MAXB];
__device__ unsigned g_mask[MAXB * 256];
__device__ float    g_pA[4][MAXB * KAB];    // txty, twth, objc, cls
__device__ float    g_pB[MAXB * NTILE];     // noobj
__device__ unsigned g_done;

__device__ __forceinline__ float softplusf(float x) {
    return fmaxf(x, 0.0f) + log1pf(expf(-fabsf(x)));
}
__device__ __forceinline__ float sigmoidf_(float x) {
    return 1.0f / (1.0f + expf(-x));
}
__device__ __forceinline__ void select5(int k, float4 v0, float4 v1, float* o) {
    switch (k) {
        case 0: o[0]=v0.x; o[1]=v0.y; o[2]=v0.z; o[3]=v0.w; o[4]=v1.x; break;
        case 1: o[0]=v0.y; o[1]=v0.z; o[2]=v0.w; o[3]=v1.x; o[4]=v1.y; break;
        case 2: o[0]=v0.z; o[1]=v0.w; o[2]=v1.x; o[3]=v1.y; o[4]=v1.z; break;
        default:o[0]=v0.w; o[1]=v1.x; o[2]=v1.y; o[3]=v1.z; o[4]=v1.w; break;
    }
}
__device__ __forceinline__ float warpRedF(float v) {
    #pragma unroll
    for (int o = 16; o > 0; o >>= 1) v += __shfl_down_sync(0xffffffffu, v, o);
    return v;
}

// ===== kA: fused conf scan + GT gather + obj losses (warp-cooperative) =====
__global__ void __launch_bounds__(KAT) kA(const float* __restrict__ preds,
                                          const float* __restrict__ targets,
                                          const float* __restrict__ anchors) {
    int b    = blockIdx.y;
    int tid  = threadIdx.x;
    int lane = tid & 31, wid = tid >> 5;
    int nbase = blockIdx.x * (KAT * KAI) + tid;

    // front-batched conf loads (MLP = 8)
    float confv[KAI];
    #pragma unroll
    for (int i = 0; i < KAI; i++) {
        int n = nbase + i * KAT;
        confv[i] = (n < NCELL) ? __ldg(targets + ((size_t)b * NCELL + n) * REC + 4) : 0.0f;
    }

    float txty = 0.f, twth = 0.f, objc = 0.f, clsl = 0.f;

    #pragma unroll
    for (int i = 0; i < KAI; i++) {
        int n = nbase + i * KAT;
        unsigned bal = __ballot_sync(0xffffffffu, confv[i] > 0.0f);
        if (lane == 0) g_mask[b * 256 + (n >> 5)] = bal;   // n < 8192 -> word < 256
        int nwbase = n - lane;

        while (bal) {   // uniform across warp
            int src = __ffs(bal) - 1;
            bal &= bal - 1;
            int ns = nwbase + src;
            float conf = __shfl_sync(0xffffffffu, confv[i], src);
            size_t f = ((size_t)b * NCELL + ns) * REC;
            const float* p = preds + f;
            const float* t = targets + f;

            // class BCE, lane-parallel: c = 5+l, 37+l, 69+l(<85)
            {
                float x, tc;
                x = __ldg(p + 5 + lane);  tc = __ldg(t + 5 + lane);
                clsl += softplusf(x) - x * tc;
                x = __ldg(p + 37 + lane); tc = __ldg(t + 37 + lane);
                clsl += softplusf(x) - x * tc;
                if (lane < 16) {
                    x = __ldg(p + 69 + lane); tc = __ldg(t + 69 + lane);
                    clsl += softplusf(x) - x * tc;
                }
            }

            if (lane == 0) {
                int a    = ns % 3;
                int cell = ns / 3;
                float fgx = (float)(cell % GSZ);
                float fgy = (float)(cell / GSZ);
                float aw = __ldg(anchors + a * 2 + 0);
                float ah = __ldg(anchors + a * 2 + 1);

                float tx = __ldg(t),   ty = __ldg(t+1), tw = __ldg(t+2), th = __ldg(t+3);
                float rx = __ldg(p),   ry = __ldg(p+1), rw = __ldg(p+2), rh = __ldg(p+3);
                float rc = __ldg(p+4);

                int slot = atomicAdd(&g_cnt[b], 1);
                if (slot < MAXGT) g_gt[b][slot] = make_float4(tx, ty, tw, th);

                float sx = sigmoidf_(rx), sy = sigmoidf_(ry);
                float bx = (sx + fgx) * RATIO;
                float by = (sy + fgy) * RATIO;
                float pxn = bx / RATIO - fgx;
                float pyn = by / RATIO - fgy;
                float txn = tx / RATIO - fgx;
                float tyn = ty / RATIO - fgy;
                float scale = 2.0f - ((tw / IMGSZ) * th) / IMGSZ;
                float dx = pxn - txn, dy = pyn - tyn;
                txty += (dx * dx) * scale + (dy * dy) * scale;

                float bw = expf(rw) * aw, bh = expf(rh) * ah;
                float pwn = bw / aw, phn = bh / ah;
                float twn = tw / aw, thn = th / ah;
                twn = (twn == 0.0f) ? 1.0f : twn;
                thn = (thn == 0.0f) ? 1.0f : thn;
                pwn = (pwn == 0.0f) ? 1.0f : pwn;
                phn = (phn == 0.0f) ? 1.0f : phn;
                twn = logf(fminf(fmaxf(twn, 1e-9f), 1e9f));
                thn = logf(fminf(fmaxf(thn, 1e-9f), 1e9f));
                pwn = logf(fminf(fmaxf(pwn, 1e-9f), 1e9f));
                phn = logf(fminf(fmaxf(phn, 1e-9f), 1e9f));
                float dw = pwn - twn, dh = phn - thn;
                twth += (dw * dw) * scale + (dh * dh) * scale;

                objc += softplusf(rc) - rc * conf;
            }
        }
    }

    __shared__ float sred[8][4];
    txty = warpRedF(txty); twth = warpRedF(twth);
    objc = warpRedF(objc); clsl = warpRedF(clsl);
    if (lane == 0) { sred[wid][0]=txty; sred[wid][1]=twth; sred[wid][2]=objc; sred[wid][3]=clsl; }
    __syncthreads();
    if (wid == 0) {
        float v0 = (lane < 8) ? sred[lane][0] : 0.f;
        float v1 = (lane < 8) ? sred[lane][1] : 0.f;
        float v2 = (lane < 8) ? sred[lane][2] : 0.f;
        float v3 = (lane < 8) ? sred[lane][3] : 0.f;
        #pragma unroll
        for (int o = 4; o > 0; o >>= 1) {
            v0 += __shfl_down_sync(0xffffffffu, v0, o);
            v1 += __shfl_down_sync(0xffffffffu, v1, o);
            v2 += __shfl_down_sync(0xffffffffu, v2, o);
            v3 += __shfl_down_sync(0xffffffffu, v3, o);
        }
        if (lane == 0) {
            int pb = b * KAB + blockIdx.x;
            g_pA[0][pb]=v0; g_pA[1][pb]=v1; g_pA[2][pb]=v2; g_pA[3][pb]=v3;
        }
    }
}

// ===== kB: noobj loss with 2D tiles + safe GT pruning; final reduce =====
__global__ void __launch_bounds__(KBT) kB(const float* __restrict__ preds,
                                          const float* __restrict__ anchors,
                                          float* __restrict__ out, int B) {
    __shared__ float4 sbox[MAXGT];
    __shared__ float  scadd[MAXGT];
    __shared__ float  sanch[6];
    __shared__ int    scand;
    __shared__ float  sred[6];

    int b    = blockIdx.y;
    int tile = blockIdx.x;
    int tx0  = (tile % TILES) * TX;
    int ty0  = (tile / TILES) * TY;
    int tid  = threadIdx.x;
    int lane = tid & 31, wid = tid >> 5;

    if (tid == 0) scand = 0;
    if (tid < 6)  sanch[tid] = anchors[tid];
    __syncthreads();

    int cnt = min(g_cnt[b], MAXGT);
    if (tid < cnt) {
        float4 g = g_gt[b][tid];
        float x_lo = tx0 * 8.0f;
        float x_hi = (float)min(tx0 + TX, GSZ) * 8.0f;
        float y_lo = ty0 * 8.0f;
        float y_hi = (float)min(ty0 + TY, GSZ) * 8.0f;
        // necessary condition for IoU>=0.6: |bx-gx| <= gw/3, |by-gy| <= gh/3
        float mx = 0.35f * g.z + 0.02f;
        float my = 0.35f * g.w + 0.02f;
        if (g.x >= x_lo - mx && g.x <= x_hi + mx &&
            g.y >= y_lo - my && g.y <= y_hi + my) {
            int pos = atomicAdd(&scand, 1);
            sbox[pos]  = make_float4(g.x - 0.5f*g.z, g.y - 0.5f*g.w,
                                     g.x + 0.5f*g.z, g.y + 0.5f*g.w);
            scadd[pos] = 0.375f * (g.z * g.w + 1e-9f);
        }
    }
    __syncthreads();
    int ncand = scand;

    float contrib = 0.0f;
    int cell = tid / 3, a = tid - cell * 3;
    int cx = tx0 + (cell & 7);
    int cy = ty0 + (cell >> 3);

    if (cx < GSZ && cy < GSZ) {
        int n = (cy * GSZ + cx) * 3 + a;
        unsigned w = g_mask[b * 256 + (n >> 5)];
        if (!((w >> (n & 31)) & 1u)) {
            size_t rec = (size_t)b * NCELL + n;
            int k = (int)(rec & 3);
            size_t f  = rec * (size_t)REC;
            size_t a4 = (f - k) >> 2;
            float4 v0 = __ldg((const float4*)preds + a4);
            float4 v1 = __ldg((const float4*)preds + a4 + 1);
            float p5[5];
            select5(k, v0, v1, p5);

            float bx = (sigmoidf_(p5[0]) + (float)cx) * RATIO;
            float by = (sigmoidf_(p5[1]) + (float)cy) * RATIO;
            float bw = expf(p5[2]) * sanch[a * 2 + 0];
            float bh = expf(p5[3]) * sanch[a * 2 + 1];

            float px0 = bx - bw * 0.5f, px1 = bx + bw * 0.5f;
            float py0 = by - bh * 0.5f, py1 = by + bh * 0.5f;
            float apq = 0.375f * (bw * bh);

            bool hit = false;
            for (int i = 0; i < ncand; i++) {
                float4 g = sbox[i];
                float iw = fmaxf(fminf(px1, g.z) - fmaxf(px0, g.x), 0.0f);
                float ih = fmaxf(fminf(py1, g.w) - fmaxf(py0, g.y), 0.0f);
                float inter = iw * ih;
                // iou >= 0.6  <=>  inter >= 0.375*(ap + ag + 1e-9)
                hit = hit | (inter >= apq + scadd[i]);
            }
            if (!hit) contrib = softplusf(p5[4]);   // conf_t == 0 here
        }
    }

    contrib = warpRedF(contrib);
    if (lane == 0) sred[wid] = contrib;
    __syncthreads();
    if (wid == 0) {
        float v = (lane < 6) ? sred[lane] : 0.f;
        #pragma unroll
        for (int o = 4; o > 0; o >>= 1) v += __shfl_down_sync(0xffffffffu, v, o);
        if (lane == 0) g_pB[b * NTILE + tile] = v;
    }

    // ---- last-block final reduction ----
    __threadfence();
    __shared__ bool amLast;
    if (tid == 0) {
        unsigned v = atomicAdd(&g_done, 1u);
        amLast = (v == (unsigned)(NTILE * gridDim.y) - 1u);
    }
    __syncthreads();
    if (!amLast) return;

    double s0=0, s1=0, s2=0, s3=0, s4=0;
    for (int i = tid; i < NTILE * B; i += KBT) s2 += (double)g_pB[i];
    for (int i = tid; i < KAB * B; i += KBT) {
        s0 += (double)g_pA[0][i];
        s1 += (double)g_pA[1][i];
        s3 += (double)g_pA[2][i];
        s4 += (double)g_pA[3][i];
    }
    __shared__ double sw[6];
    double vals[5] = {s0, s1, s2, s3, s4};
    double res[5];
    #pragma unroll
    for (int j = 0; j < 5; j++) {
        double v = vals[j];
        #pragma unroll
        for (int o = 16; o > 0; o >>= 1) v += __shfl_down_sync(0xffffffffu, v, o);
        if (lane == 0) sw[wid] = v;
        __syncthreads();
        v = (tid < 6) ? sw[tid] : 0.0;
        if (wid == 0) {
            #pragma unroll
            for (int o = 4; o > 0; o >>= 1) v += __shfl_down_sync(0xffffffffu, v, o);
        }
        res[j] = v;
        __syncthreads();
    }
    if (tid == 0) {
        float v0 = (float)(res[0] / (double)B);
        float v1 = (float)(res[1] / (double)B);
        float v2 = (float)(res[2] / (double)B);
        float v3 = (float)(res[3] / (double)B);
        float v4 = (float)(res[4] / (double)B);
        out[0]=v0; out[1]=v1; out[2]=v2; out[3]=v3; out[4]=v4;
        out[5] = (((v0 + v1) + v2) + v3) + v4;
        g_done = 0;
    }
    if (tid < MAXB) g_cnt[tid] = 0;
}

extern "C" void kernel_launch(void* const* d_in, const int* in_sizes, int n_in,
                              void* d_out, int out_size) {
    const float* preds   = (const float*)d_in[0];
    const float* targets = (const float*)d_in[1];
    const float* anchors = (const float*)d_in[2];
    float* out = (float*)d_out;

    int B = in_sizes[0] / (NCELL * REC);
    if (B > MAXB) B = MAXB;

    dim3 gA(KAB, B);
    kA<<<gA, KAT>>>(preds, targets, anchors);
    dim3 gB(NTILE, B);
    kB<<<gB, KBT>>>(preds, anchors, out, B);
}

// round 5
// speedup vs baseline: 1.2630x; 1.2630x over previous
#include <cuda_runtime.h>

#define GSZ   52
#define NANCH 3
#define NCELL (GSZ * GSZ * NANCH)   // 8112
#define REC   85
#define MAXB  64
#define MAXGT 64
#define IMGSZ 416.0f
#define RATIO 8.0f
#define KAB   8                     // kA blocks per batch
#define KAT   256
#define KAI   4                     // 8*256*4 = 8192 >= 8112
#define TX    8
#define TY    8
#define TILES 7
#define NTILE (TILES * TILES)       // 49
#define KBT   192
#define OBJB  11                    // obj blocks per batch: 11*6 warps = 66 >= 64 slots
#define GBX   (NTILE + OBJB)        // 60

// ---- scratch (device globals; zero-init at load) ----
__device__ float4   g_gt[MAXB][MAXGT];
__device__ int      g_idx[MAXB][MAXGT];
__device__ int      g_cnt[MAXB];
__device__ unsigned g_mask[MAXB * 256];
__device__ float    g_pA[4][MAXB * OBJB];   // txty, twth, objc, cls
__device__ float    g_pB[MAXB * NTILE];     // noobj
__device__ unsigned g_done;

__device__ __forceinline__ float softplusf(float x) {
    return fmaxf(x, 0.0f) + log1pf(expf(-fabsf(x)));
}
__device__ __forceinline__ float sigmoidf_(float x) {
    return 1.0f / (1.0f + expf(-x));
}
__device__ __forceinline__ void select5(int k, float4 v0, float4 v1, float* o) {
    switch (k) {
        case 0: o[0]=v0.x; o[1]=v0.y; o[2]=v0.z; o[3]=v0.w; o[4]=v1.x; break;
        case 1: o[0]=v0.y; o[1]=v0.z; o[2]=v0.w; o[3]=v1.x; o[4]=v1.y; break;
        case 2: o[0]=v0.z; o[1]=v0.w; o[2]=v1.x; o[3]=v1.y; o[4]=v1.z; break;
        default:o[0]=v0.w; o[1]=v1.x; o[2]=v1.y; o[3]=v1.z; o[4]=v1.w; break;
    }
}
__device__ __forceinline__ float warpRedF(float v) {
    #pragma unroll
    for (int o = 16; o > 0; o >>= 1) v += __shfl_down_sync(0xffffffffu, v, o);
    return v;
}

// ===== kA: coarsened conf scan -> ballot mask + GT gather =====
__global__ void __launch_bounds__(KAT) kA(const float* __restrict__ targets) {
    int b = blockIdx.y;
    int nbase = blockIdx.x * (KAT * KAI) + threadIdx.x;

    float confv[KAI];
    #pragma unroll
    for (int i = 0; i < KAI; i++) {
        int n = nbase + i * KAT;
        confv[i] = (n < NCELL) ? __ldg(targets + ((size_t)b * NCELL + n) * REC + 4) : 0.0f;
    }

    #pragma unroll
    for (int i = 0; i < KAI; i++) {
        int n = nbase + i * KAT;
        unsigned bal = __ballot_sync(0xffffffffu, confv[i] > 0.0f);
        if ((threadIdx.x & 31) == 0) g_mask[b * 256 + (n >> 5)] = bal;
        if (confv[i] > 0.0f) {
            int slot = atomicAdd(&g_cnt[b], 1);
            if (slot < MAXGT) {
                const float* r = targets + ((size_t)b * NCELL + n) * REC;
                g_gt[b][slot]  = make_float4(__ldg(r), __ldg(r+1), __ldg(r+2), __ldg(r+3));
                g_idx[b][slot] = n;
            }
        }
    }
}

// ===== kB: tiles (noobj) + obj blocks + last-block final reduce =====
__global__ void __launch_bounds__(KBT) kB(const float* __restrict__ preds,
                                          const float* __restrict__ targets,
                                          const float* __restrict__ anchors,
                                          float* __restrict__ out, int B) {
    int b    = blockIdx.y;
    int tid  = threadIdx.x;
    int lane = tid & 31, wid = tid >> 5;
    int cnt  = min(g_cnt[b], MAXGT);

    if (blockIdx.x < NTILE) {
        // ---------- noobj tile ----------
        __shared__ float4 sbox[MAXGT];
        __shared__ float  scadd[MAXGT];
        __shared__ float  sanch[6];
        __shared__ int    scand;
        __shared__ float  sred[6];

        int tile = blockIdx.x;
        int tx0  = (tile % TILES) * TX;
        int ty0  = (tile / TILES) * TY;

        if (tid == 0) scand = 0;
        if (tid < 6)  sanch[tid] = anchors[tid];
        __syncthreads();

        if (tid < cnt) {
            float4 g = g_gt[b][tid];
            float x_lo = tx0 * 8.0f;
            float x_hi = (float)min(tx0 + TX, GSZ) * 8.0f;
            float y_lo = ty0 * 8.0f;
            float y_hi = (float)min(ty0 + TY, GSZ) * 8.0f;
            float mx = 0.35f * g.z + 0.02f;     // |bx-gx|<=gw/3 necessary for IoU>=0.6
            float my = 0.35f * g.w + 0.02f;
            if (g.x >= x_lo - mx && g.x <= x_hi + mx &&
                g.y >= y_lo - my && g.y <= y_hi + my) {
                int pos = atomicAdd(&scand, 1);
                sbox[pos]  = make_float4(g.x - 0.5f*g.z, g.y - 0.5f*g.w,
                                         g.x + 0.5f*g.z, g.y + 0.5f*g.w);
                scadd[pos] = 0.375f * (g.z * g.w + 1e-9f);
            }
        }
        __syncthreads();
        int ncand = scand;

        float contrib = 0.0f;
        int cell = tid / 3, a = tid - cell * 3;
        int cx = tx0 + (cell & 7);
        int cy = ty0 + (cell >> 3);

        if (cx < GSZ && cy < GSZ) {
            int n = (cy * GSZ + cx) * 3 + a;
            size_t rec = (size_t)b * NCELL + n;
            int k = (int)(rec & 3);
            size_t f  = rec * (size_t)REC;
            size_t a4 = (f - k) >> 2;
            // issue all 3 loads up front (MLP=3), gate only the compute
            float4 v0 = __ldg((const float4*)preds + a4);
            float4 v1 = __ldg((const float4*)preds + a4 + 1);
            unsigned w = g_mask[b * 256 + (n >> 5)];
            if (!((w >> (n & 31)) & 1u)) {
                float p5[5];
                select5(k, v0, v1, p5);
                float bx = (sigmoidf_(p5[0]) + (float)cx) * RATIO;
                float by = (sigmoidf_(p5[1]) + (float)cy) * RATIO;
                float bw = expf(p5[2]) * sanch[a * 2 + 0];
                float bh = expf(p5[3]) * sanch[a * 2 + 1];
                float px0 = bx - bw * 0.5f, px1 = bx + bw * 0.5f;
                float py0 = by - bh * 0.5f, py1 = by + bh * 0.5f;
                float apq = 0.375f * (bw * bh);
                bool hit = false;
                for (int i = 0; i < ncand; i++) {
                    float4 g = sbox[i];
                    float iw = fmaxf(fminf(px1, g.z) - fmaxf(px0, g.x), 0.0f);
                    float ih = fmaxf(fminf(py1, g.w) - fmaxf(py0, g.y), 0.0f);
                    float inter = iw * ih;
                    hit = hit | (inter >= apq + scadd[i]);   // iou>=0.6
                }
                if (!hit) contrib = softplusf(p5[4]);        // conf_t == 0 here
            }
        }

        contrib = warpRedF(contrib);
        if (lane == 0) sred[wid] = contrib;
        __syncthreads();
        if (wid == 0) {
            float v = (lane < 6) ? sred[lane] : 0.f;
            #pragma unroll
            for (int o = 4; o > 0; o >>= 1) v += __shfl_down_sync(0xffffffffu, v, o);
            if (lane == 0) g_pB[b * NTILE + tile] = v;
        }
    } else {
        // ---------- obj losses: one warp per GT slot ----------
        __shared__ float sredo[6][4];
        int ob   = blockIdx.x - NTILE;
        int slot = ob * 6 + wid;

        float txty = 0.f, twth = 0.f, objc = 0.f, clsl = 0.f;

        if (slot < cnt) {
            int n = g_idx[b][slot];
            size_t f = ((size_t)b * NCELL + n) * REC;
            const float* p = preds + f;
            const float* t = targets + f;

            float x, tc;
            x = __ldg(p + 5 + lane);  tc = __ldg(t + 5 + lane);
            clsl += softplusf(x) - x * tc;
            x = __ldg(p + 37 + lane); tc = __ldg(t + 37 + lane);
            clsl += softplusf(x) - x * tc;
            if (lane < 16) {
                x = __ldg(p + 69 + lane); tc = __ldg(t + 69 + lane);
                clsl += softplusf(x) - x * tc;
            }

            if (lane == 0) {
                int a    = n % 3;
                int cell = n / 3;
                float fgx = (float)(cell % GSZ);
                float fgy = (float)(cell / GSZ);
                float aw = __ldg(anchors + a * 2 + 0);
                float ah = __ldg(anchors + a * 2 + 1);

                float rx = __ldg(p), ry = __ldg(p+1), rw = __ldg(p+2), rh = __ldg(p+3), rc = __ldg(p+4);
                float tx = __ldg(t), ty = __ldg(t+1), tw = __ldg(t+2), th = __ldg(t+3), conf = __ldg(t+4);

                float sx = sigmoidf_(rx), sy = sigmoidf_(ry);
                float bx = (sx + fgx) * RATIO;
                float by = (sy + fgy) * RATIO;
                float pxn = bx / RATIO - fgx;
                float pyn = by / RATIO - fgy;
                float txn = tx / RATIO - fgx;
                float tyn = ty / RATIO - fgy;
                float scale = 2.0f - ((tw / IMGSZ) * th) / IMGSZ;
                float dx = pxn - txn, dy = pyn - tyn;
                txty = (dx * dx) * scale + (dy * dy) * scale;

                float bw = expf(rw) * aw, bh = expf(rh) * ah;
                float pwn = bw / aw, phn = bh / ah;
                float twn = tw / aw, thn = th / ah;
                twn = (twn == 0.0f) ? 1.0f : twn;
                thn = (thn == 0.0f) ? 1.0f : thn;
                pwn = (pwn == 0.0f) ? 1.0f : pwn;
                phn = (phn == 0.0f) ? 1.0f : phn;
                twn = logf(fminf(fmaxf(twn, 1e-9f), 1e9f));
                thn = logf(fminf(fmaxf(thn, 1e-9f), 1e9f));
                pwn = logf(fminf(fmaxf(pwn, 1e-9f), 1e9f));
                phn = logf(fminf(fmaxf(phn, 1e-9f), 1e9f));
                float dw = pwn - twn, dh = phn - thn;
                twth = (dw * dw) * scale + (dh * dh) * scale;

                objc = softplusf(rc) - rc * conf;
            }
        }

        txty = warpRedF(txty); twth = warpRedF(twth);
        objc = warpRedF(objc); clsl = warpRedF(clsl);
        if (lane == 0) { sredo[wid][0]=txty; sredo[wid][1]=twth; sredo[wid][2]=objc; sredo[wid][3]=clsl; }
        __syncthreads();
        if (wid == 0) {
            float v0 = (lane < 6) ? sredo[lane][0] : 0.f;
            float v1 = (lane < 6) ? sredo[lane][1] : 0.f;
            float v2 = (lane < 6) ? sredo[lane][2] : 0.f;
            float v3 = (lane < 6) ? sredo[lane][3] : 0.f;
            #pragma unroll
            for (int o = 4; o > 0; o >>= 1) {
                v0 += __shfl_down_sync(0xffffffffu, v0, o);
                v1 += __shfl_down_sync(0xffffffffu, v1, o);
                v2 += __shfl_down_sync(0xffffffffu, v2, o);
                v3 += __shfl_down_sync(0xffffffffu, v3, o);
            }
            if (lane == 0) {
                int pb = b * OBJB + ob;
                g_pA[0][pb]=v0; g_pA[1][pb]=v1; g_pA[2][pb]=v2; g_pA[3][pb]=v3;
            }
        }
    }

    // ---- last-block final reduction ----
    __threadfence();
    __shared__ bool amLast;
    if (tid == 0) {
        unsigned v = atomicAdd(&g_done, 1u);
        amLast = (v == (unsigned)(GBX * gridDim.y) - 1u);
    }
    __syncthreads();
    if (!amLast) return;

    double s0=0, s1=0, s2=0, s3=0, s4=0;
    for (int i = tid; i < NTILE * B; i += KBT) s2 += (double)g_pB[i];
    for (int i = tid; i < OBJB * B; i += KBT) {
        s0 += (double)g_pA[0][i];
        s1 += (double)g_pA[1][i];
        s3 += (double)g_pA[2][i];
        s4 += (double)g_pA[3][i];
    }
    __shared__ double sw[6];
    double vals[5] = {s0, s1, s2, s3, s4};
    double res[5];
    #pragma unroll
    for (int j = 0; j < 5; j++) {
        double v = vals[j];
        #pragma unroll
        for (int o = 16; o > 0; o >>= 1) v += __shfl_down_sync(0xffffffffu, v, o);
        if (lane == 0) sw[wid] = v;
        __syncthreads();
        v = (tid < 6) ? sw[tid] : 0.0;
        if (wid == 0) {
            #pragma unroll
            for (int o = 4; o > 0; o >>= 1) v += __shfl_down_sync(0xffffffffu, v, o);
        }
        res[j] = v;
        __syncthreads();
    }
    if (tid == 0) {
        float v0 = (float)(res[0] / (double)B);
        float v1 = (float)(res[1] / (double)B);
        float v2 = (float)(res[2] / (double)B);
        float v3 = (float)(res[3] / (double)B);
        float v4 = (float)(res[4] / (double)B);
        out[0]=v0; out[1]=v1; out[2]=v2; out[3]=v3; out[4]=v4;
        out[5] = (((v0 + v1) + v2) + v3) + v4;
        g_done = 0;
    }
    if (tid < MAXB) g_cnt[tid] = 0;
}

extern "C" void kernel_launch(void* const* d_in, const int* in_sizes, int n_in,
                              void* d_out, int out_size) {
    const float* preds   = (const float*)d_in[0];
    const float* targets = (const float*)d_in[1];
    const float* anchors = (const float*)d_in[2];
    float* out = (float*)d_out;

    int B = in_sizes[0] / (NCELL * REC);
    if (B > MAXB) B = MAXB;

    dim3 gA(KAB, B);
    kA<<<gA, KAT>>>(targets);
    dim3 gB(GBX, B);
    kB<<<gB, KBT>>>(preds, targets, anchors, out, B);
}

// round 6
// speedup vs baseline: 1.3875x; 1.0986x over previous
#include <cuda_runtime.h>

#define GSZ   52
#define NANCH 3
#define NCELL (GSZ * GSZ * NANCH)   // 8112
#define REC   85
#define MAXB  64
#define MAXGT 64
#define IMGSZ 416.0f
#define RATIO 8.0f
#define KAB   8
#define KAT   256
#define KAI   4                     // 8*256*4 = 8192 >= 8112
#define TX    8
#define TY    8
#define TILES 7
#define NTILE (TILES * TILES)       // 49
#define KBT   192
#define OBJB  11                    // 11*6 warps = 66 >= 64 slots
#define GBX   (NTILE + OBJB)        // 60

// ---- scratch (device globals; zero-init at load) ----
__device__ float4   g_gt[MAXB][MAXGT];
__device__ int      g_idx[MAXB][MAXGT];
__device__ int      g_cnt[MAXB];
__device__ unsigned g_mask[MAXB * 256];
__device__ float    g_pA[4][MAXB * OBJB];
__device__ float    g_pB[MAXB * NTILE];
__device__ unsigned g_done;

__device__ __forceinline__ float softplusf(float x) {
    return fmaxf(x, 0.0f) + log1pf(expf(-fabsf(x)));
}
__device__ __forceinline__ float sigmoidf_(float x) {
    return 1.0f / (1.0f + expf(-x));
}
__device__ __forceinline__ void select5(int k, float4 v0, float4 v1, float* o) {
    switch (k) {
        case 0: o[0]=v0.x; o[1]=v0.y; o[2]=v0.z; o[3]=v0.w; o[4]=v1.x; break;
        case 1: o[0]=v0.y; o[1]=v0.z; o[2]=v0.w; o[3]=v1.x; o[4]=v1.y; break;
        case 2: o[0]=v0.z; o[1]=v0.w; o[2]=v1.x; o[3]=v1.y; o[4]=v1.z; break;
        default:o[0]=v0.w; o[1]=v1.x; o[2]=v1.y; o[3]=v1.z; o[4]=v1.w; break;
    }
}
__device__ __forceinline__ float warpRedF(float v) {
    #pragma unroll
    for (int o = 16; o > 0; o >>= 1) v += __shfl_down_sync(0xffffffffu, v, o);
    return v;
}

// ===== kA: coarsened conf scan -> ballot mask + GT gather =====
__global__ void __launch_bounds__(KAT) kA(const float* __restrict__ targets) {
    int b = blockIdx.y;
    int nbase = blockIdx.x * (KAT * KAI) + threadIdx.x;

    float confv[KAI];
    #pragma unroll
    for (int i = 0; i < KAI; i++) {
        int n = nbase + i * KAT;
        confv[i] = (n < NCELL) ? __ldg(targets + ((size_t)b * NCELL + n) * REC + 4) : 0.0f;
    }

    #pragma unroll
    for (int i = 0; i < KAI; i++) {
        int n = nbase + i * KAT;
        unsigned bal = __ballot_sync(0xffffffffu, confv[i] > 0.0f);
        if ((threadIdx.x & 31) == 0) g_mask[b * 256 + (n >> 5)] = bal;
        if (confv[i] > 0.0f) {
            int slot = atomicAdd(&g_cnt[b], 1);
            if (slot < MAXGT) {
                const float* r = targets + ((size_t)b * NCELL + n) * REC;
                g_gt[b][slot]  = make_float4(__ldg(r), __ldg(r+1), __ldg(r+2), __ldg(r+3));
                g_idx[b][slot] = n;
            }
        }
    }
}

// ===== kB: tiles (noobj, with empty-tile fast path) + obj blocks + reduce ==
__global__ void __launch_bounds__(KBT) kB(const float* __restrict__ preds,
                                          const float* __restrict__ targets,
                                          const float* __restrict__ anchors,
                                          float* __restrict__ out, int B) {
    int b    = blockIdx.y;
    int tid  = threadIdx.x;
    int lane = tid & 31, wid = tid >> 5;
    int cnt  = min(g_cnt[b], MAXGT);

    if (blockIdx.x < NTILE) {
        __shared__ float4 sbox[MAXGT];
        __shared__ float  scadd[MAXGT];
        __shared__ float  sanch[6];
        __shared__ int    scand;
        __shared__ float  sred[6];

        int tile = blockIdx.x;
        int tx0  = (tile % TILES) * TX;
        int ty0  = (tile / TILES) * TY;

        if (tid == 0) scand = 0;
        if (tid < 6)  sanch[tid] = anchors[tid];
        __syncthreads();

        if (tid < cnt) {
            float4 g = g_gt[b][tid];
            float x_lo = tx0 * 8.0f;
            float x_hi = (float)min(tx0 + TX, GSZ) * 8.0f;
            float y_lo = ty0 * 8.0f;
            float y_hi = (float)min(ty0 + TY, GSZ) * 8.0f;
            // necessary for IoU>=0.6: |bx-gx| <= gw/3 (+margin), same for y
            float mx = 0.35f * g.z + 0.02f;
            float my = 0.35f * g.w + 0.02f;
            if (g.x >= x_lo - mx && g.x <= x_hi + mx &&
                g.y >= y_lo - my && g.y <= y_hi + my) {
                int pos = atomicAdd(&scand, 1);
                sbox[pos]  = make_float4(g.x - 0.5f*g.z, g.y - 0.5f*g.w,
                                         g.x + 0.5f*g.z, g.y + 0.5f*g.w);
                scadd[pos] = 0.375f * (g.z * g.w + 1e-9f);
            }
        }
        __syncthreads();
        int ncand = scand;    // uniform across block

        float contrib = 0.0f;
        int cell = tid / 3, a = tid - cell * 3;
        int cx = tx0 + (cell & 7);
        int cy = ty0 + (cell >> 3);
        bool valid = (cx < GSZ) && (cy < GSZ);
        int n = (cy * GSZ + cx) * 3 + a;
        size_t rec = (size_t)b * NCELL + n;
        size_t f   = rec * (size_t)REC;

        if (ncand == 0) {
            // fast path: no GT can reach IoU>=0.6 anywhere in this tile
            if (valid) {
                float rc = __ldg(preds + f + 4);
                unsigned w = g_mask[b * 256 + (n >> 5)];
                if (!((w >> (n & 31)) & 1u)) contrib = softplusf(rc);
            }
        } else if (valid) {
            int k = (int)(rec & 3);
            size_t a4 = (f - k) >> 2;
            float4 v0 = __ldg((const float4*)preds + a4);
            float4 v1 = __ldg((const float4*)preds + a4 + 1);
            unsigned w = g_mask[b * 256 + (n >> 5)];
            if (!((w >> (n & 31)) & 1u)) {
                float p5[5];
                select5(k, v0, v1, p5);
                float bx = (sigmoidf_(p5[0]) + (float)cx) * RATIO;
                float by = (sigmoidf_(p5[1]) + (float)cy) * RATIO;
                float bw = expf(p5[2]) * sanch[a * 2 + 0];
                float bh = expf(p5[3]) * sanch[a * 2 + 1];
                float px0 = bx - bw * 0.5f, px1 = bx + bw * 0.5f;
                float py0 = by - bh * 0.5f, py1 = by + bh * 0.5f;
                float apq = 0.375f * (bw * bh);
                bool hit = false;
                for (int i = 0; i < ncand; i++) {
                    float4 g = sbox[i];
                    float iw = fmaxf(fminf(px1, g.z) - fmaxf(px0, g.x), 0.0f);
                    float ih = fmaxf(fminf(py1, g.w) - fmaxf(py0, g.y), 0.0f);
                    float inter = iw * ih;
                    hit = hit | (inter >= apq + scadd[i]);   // iou>=0.6
                }
                if (!hit) contrib = softplusf(p5[4]);
            }
        }

        contrib = warpRedF(contrib);
        if (lane == 0) sred[wid] = contrib;
        __syncthreads();
        if (wid == 0) {
            float v = (lane < 6) ? sred[lane] : 0.f;
            #pragma unroll
            for (int o = 4; o > 0; o >>= 1) v += __shfl_down_sync(0xffffffffu, v, o);
            if (lane == 0) g_pB[b * NTILE + tile] = v;
        }
    } else {
        // ---------- obj losses: one warp per GT slot ----------
        __shared__ float sredo[6][4];
        int ob   = blockIdx.x - NTILE;
        int slot = ob * 6 + wid;

        float txty = 0.f, twth = 0.f, objc = 0.f, clsl = 0.f;

        if (slot < cnt) {
            int n = g_idx[b][slot];
            size_t f = ((size_t)b * NCELL + n) * REC;
            const float* p = preds + f;
            const float* t = targets + f;

            float x, tc;
            x = __ldg(p + 5 + lane);  tc = __ldg(t + 5 + lane);
            clsl += softplusf(x) - x * tc;
            x = __ldg(p + 37 + lane); tc = __ldg(t + 37 + lane);
            clsl += softplusf(x) - x * tc;
            if (lane < 16) {
                x = __ldg(p + 69 + lane); tc = __ldg(t + 69 + lane);
                clsl += softplusf(x) - x * tc;
            }

            if (lane == 0) {
                int a    = n % 3;
                int cell = n / 3;
                float fgx = (float)(cell % GSZ);
                float fgy = (float)(cell / GSZ);
                float aw = __ldg(anchors + a * 2 + 0);
                float ah = __ldg(anchors + a * 2 + 1);

                float rx = __ldg(p), ry = __ldg(p+1), rw = __ldg(p+2), rh = __ldg(p+3), rc = __ldg(p+4);
                float tx = __ldg(t), ty = __ldg(t+1), tw = __ldg(t+2), th = __ldg(t+3), conf = __ldg(t+4);

                float sx = sigmoidf_(rx), sy = sigmoidf_(ry);
                float bx = (sx + fgx) * RATIO;
                float by = (sy + fgy) * RATIO;
                float pxn = bx / RATIO - fgx;
                float pyn = by / RATIO - fgy;
                float txn = tx / RATIO - fgx;
                float tyn = ty / RATIO - fgy;
                float scale = 2.0f - ((tw / IMGSZ) * th) / IMGSZ;
                float dx = pxn - txn, dy = pyn - tyn;
                txty = (dx * dx) * scale + (dy * dy) * scale;

                float bw = expf(rw) * aw, bh = expf(rh) * ah;
                float pwn = bw / aw, phn = bh / ah;
                float twn = tw / aw, thn = th / ah;
                twn = (twn == 0.0f) ? 1.0f : twn;
                thn = (thn == 0.0f) ? 1.0f : thn;
                pwn = (pwn == 0.0f) ? 1.0f : pwn;
                phn = (phn == 0.0f) ? 1.0f : phn;
                twn = logf(fminf(fmaxf(twn, 1e-9f), 1e9f));
                thn = logf(fminf(fmaxf(thn, 1e-9f), 1e9f));
                pwn = logf(fminf(fmaxf(pwn, 1e-9f), 1e9f));
                phn = logf(fminf(fmaxf(phn, 1e-9f), 1e9f));
                float dw = pwn - twn, dh = phn - thn;
                twth = (dw * dw) * scale + (dh * dh) * scale;

                objc = softplusf(rc) - rc * conf;
            }
        }

        txty = warpRedF(txty); twth = warpRedF(twth);
        objc = warpRedF(objc); clsl = warpRedF(clsl);
        if (lane == 0) { sredo[wid][0]=txty; sredo[wid][1]=twth; sredo[wid][2]=objc; sredo[wid][3]=clsl; }
        __syncthreads();
        if (wid == 0) {
            float v0 = (lane < 6) ? sredo[lane][0] : 0.f;
            float v1 = (lane < 6) ? sredo[lane][1] : 0.f;
            float v2 = (lane < 6) ? sredo[lane][2] : 0.f;
            float v3 = (lane < 6) ? sredo[lane][3] : 0.f;
            #pragma unroll
            for (int o = 4; o > 0; o >>= 1) {
                v0 += __shfl_down_sync(0xffffffffu, v0, o);
                v1 += __shfl_down_sync(0xffffffffu, v1, o);
                v2 += __shfl_down_sync(0xffffffffu, v2, o);
                v3 += __shfl_down_sync(0xffffffffu, v3, o);
            }
            if (lane == 0) {
                int pb = b * OBJB + ob;
                g_pA[0][pb]=v0; g_pA[1][pb]=v1; g_pA[2][pb]=v2; g_pA[3][pb]=v3;
            }
        }
    }

    // ---- last-block final reduction ----
    __threadfence();
    __shared__ bool amLast;
    if (tid == 0) {
        unsigned v = atomicAdd(&g_done, 1u);
        amLast = (v == (unsigned)(GBX * gridDim.y) - 1u);
    }
    __syncthreads();
    if (!amLast) return;

    double s0=0, s1=0, s2=0, s3=0, s4=0;
    for (int i = tid; i < NTILE * B; i += KBT) s2 += (double)g_pB[i];
    for (int i = tid; i < OBJB * B; i += KBT) {
        s0 += (double)g_pA[0][i];
        s1 += (double)g_pA[1][i];
        s3 += (double)g_pA[2][i];
        s4 += (double)g_pA[3][i];
    }
    __shared__ double sw[6];
    double vals[5] = {s0, s1, s2, s3, s4};
    double res[5];
    #pragma unroll
    for (int j = 0; j < 5; j++) {
        double v = vals[j];
        #pragma unroll
        for (int o = 16; o > 0; o >>= 1) v += __shfl_down_sync(0xffffffffu, v, o);
        if (lane == 0) sw[wid] = v;
        __syncthreads();
        v = (tid < 6) ? sw[tid] : 0.0;
        if (wid == 0) {
            #pragma unroll
            for (int o = 4; o > 0; o >>= 1) v += __shfl_down_sync(0xffffffffu, v, o);
        }
        res[j] = v;
        __syncthreads();
    }
    if (tid == 0) {
        float v0 = (float)(res[0] / (double)B);
        float v1 = (float)(res[1] / (double)B);
        float v2 = (float)(res[2] / (double)B);
        float v3 = (float)(res[3] / (double)B);
        float v4 = (float)(res[4] / (double)B);
        out[0]=v0; out[1]=v1; out[2]=v2; out[3]=v3; out[4]=v4;
        out[5] = (((v0 + v1) + v2) + v3) + v4;
        g_done = 0;
    }
    if (tid < MAXB) g_cnt[tid] = 0;
}

extern "C" void kernel_launch(void* const* d_in, const int* in_sizes, int n_in,
                              void* d_out, int out_size) {
    const float* preds   = (const float*)d_in[0];
    const float* targets = (const float*)d_in[1];
    const float* anchors = (const float*)d_in[2];
    float* out = (float*)d_out;

    int B = in_sizes[0] / (NCELL * REC);
    if (B > MAXB) B = MAXB;

    dim3 gA(KAB, B);
    kA<<<gA, KAT>>>(targets);
    dim3 gB(GBX, B);
    kB<<<gB, KBT>>>(preds, targets, anchors, out, B);
}